// round 16
// baseline (speedup 1.0000x reference)
#include <cuda_runtime.h>
#include <cuda_fp16.h>
#include <cstdint>

#define N_NODES 100000
#define N_EDGES 1600000
#define HIDDEN  64
#define SCAN_B  1024
#define NBLK    ((N_NODES + SCAN_B - 1) / SCAN_B)   // 98

// ---------------- scratch (static device globals; no runtime alloc) -------
// agg8 layout: [ea0, ea1, ea2, deg, x0, x1, x2, pad]
__device__ __align__(256) float  g_agg8[N_NODES * 8];
__device__ __align__(256) __half g_hh[N_NODES * HIDDEN];   // layer-1 output (fp16)
__device__ __align__(256) float  g_aggh[N_NODES * HIDDEN]; // layer-2 neighbor sum
__device__ __align__(256) int    g_src[N_EDGES];
__device__ __align__(256) int    g_dst[N_EDGES];
__device__ __align__(256) int    g_csr_src[N_EDGES];       // src ids grouped by dst
__device__ __align__(256) int    g_rowptr[N_NODES + 1];
__device__ __align__(256) int    g_fill[N_NODES];
__device__ __align__(256) int    g_blocksum[128];
__device__ __align__(256) int    g_blockoff[128];
__device__ int g_is64;

__device__ __forceinline__ void red_add_v4(float* addr, float a, float b, float c, float d) {
    asm volatile(
        "{ .reg .u64 p; cvta.to.global.u64 p, %0;\n"
        "  red.global.add.v4.f32 [p], {%1, %2, %3, %4}; }\n"
        :: "l"(addr), "f"(a), "f"(b), "f"(c), "f"(d) : "memory");
}

// packed f32x2 helpers (FFMA2 path)
#define PACK2(out, v) \
    asm("mov.b64 %0, {%1, %1};" : "=l"(out) : "f"(v))
#define FMA2(d, a, b, c) \
    asm("fma.rn.f32x2 %0, %1, %2, %3;" : "=l"(d) : "l"(a), "l"(b), "l"(c))
#define UNPACK2(lo, hi, in) \
    asm("mov.b64 {%0, %1}, %2;" : "=f"(lo), "=f"(hi) : "l"(in))

// ---------------- K0: detect edge_index dtype (parallel) -------------------
__global__ void k_detect(const int* __restrict__ ei32) {
    int lane = threadIdx.x;
    int nz = 0;
    if (ei32[4 * lane + 1] != 0) nz = 1;
    if (ei32[4 * lane + 3] != 0) nz = 1;
    unsigned m = __ballot_sync(0xffffffffu, nz);
    if (lane == 0) g_is64 = (m == 0) ? 1 : 0;
}

// ---------------- K1: zero agg8 --------------------------------------------
__global__ void k_zero() {
    int i = blockIdx.x * blockDim.x + threadIdx.x;
    int stride = gridDim.x * blockDim.x;
    float4 z = make_float4(0.f, 0.f, 0.f, 0.f);
    for (int t = i; t < (N_NODES * 8) / 4; t += stride)
        reinterpret_cast<float4*>(g_agg8)[t] = z;
}

// ---------------- K2: edge pass 1 — ONE red.v4 per edge (ea + deg) ---------
__global__ void k_edge1(const void* __restrict__ ei,
                        const float* __restrict__ ea) {
    int t = blockIdx.x * blockDim.x + threadIdx.x;
    int e = 2 * t;
    if (e >= N_EDGES) return;
    int s0, s1, d0, d1;
    if (g_is64) {
        const longlong2* ps = (const longlong2*)ei;
        longlong2 sp = ps[t];
        longlong2 dp = ps[(N_EDGES / 2) + t];
        s0 = (int)sp.x; s1 = (int)sp.y;
        d0 = (int)dp.x; d1 = (int)dp.y;
    } else {
        const int2* ps = (const int2*)ei;
        int2 sp = ps[t];
        int2 dp = ps[(N_EDGES / 2) + t];
        s0 = sp.x; s1 = sp.y;
        d0 = dp.x; d1 = dp.y;
    }
    reinterpret_cast<int2*>(g_src)[t] = make_int2(s0, s1);
    reinterpret_cast<int2*>(g_dst)[t] = make_int2(d0, d1);

    const float2* pea = (const float2*)(ea + 6 * (size_t)t);
    float2 a01 = pea[0];   // e0: ea0 ea1
    float2 a23 = pea[1];   // e0: ea2 | e1: ea0
    float2 a45 = pea[2];   // e1: ea1 ea2

    red_add_v4(&g_agg8[(size_t)d0 * 8], a01.x, a01.y, a23.x, 1.0f);
    red_add_v4(&g_agg8[(size_t)d1 * 8], a23.y, a45.x, a45.y, 1.0f);
}

// ---------------- K3a: per-block scan of degrees (deg at slot 3) -----------
__global__ void k_scan_blk() {
    __shared__ int sh[SCAN_B];
    int t = threadIdx.x;
    int i = blockIdx.x * SCAN_B + t;
    int d = (i < N_NODES) ? (int)g_agg8[(size_t)i * 8 + 3] : 0;
    sh[t] = d;
    __syncthreads();
    #pragma unroll
    for (int off = 1; off < SCAN_B; off <<= 1) {
        int v = (t >= off) ? sh[t - off] : 0;
        __syncthreads();
        sh[t] += v;
        __syncthreads();
    }
    if (i < N_NODES) g_rowptr[i] = sh[t] - d;
    if (t == SCAN_B - 1) g_blocksum[blockIdx.x] = sh[t];
}

// ---------------- K3b: scan of the block sums ------------------------------
__global__ void k_scan_top() {
    __shared__ int sh[128];
    int t = threadIdx.x;
    int v = (t < NBLK) ? g_blocksum[t] : 0;
    sh[t] = v;
    __syncthreads();
    #pragma unroll
    for (int off = 1; off < 128; off <<= 1) {
        int u = (t >= off) ? sh[t - off] : 0;
        __syncthreads();
        sh[t] += u;
        __syncthreads();
    }
    if (t < NBLK) g_blockoff[t] = sh[t] - v;
    if (t == 127) g_rowptr[N_NODES] = sh[127];
}

// ---------------- K3c: add block offsets; init fill cursors ----------------
__global__ void k_scan_add() {
    int i = blockIdx.x * blockDim.x + threadIdx.x;
    if (i >= N_NODES) return;
    int r = g_rowptr[i] + g_blockoff[i >> 10];
    g_rowptr[i] = r;
    g_fill[i]   = r;
}

// ---------------- K4: scatter src ids into dst-grouped CSR (2 edges/thr) ---
__global__ void k_scatter() {
    int t = blockIdx.x * blockDim.x + threadIdx.x;
    if (2 * t >= N_EDGES) return;
    int2 s = reinterpret_cast<const int2*>(g_src)[t];
    int2 d = reinterpret_cast<const int2*>(g_dst)[t];
    int p0 = atomicAdd(&g_fill[d.x], 1);
    g_csr_src[p0] = s.x;
    int p1 = atomicAdd(&g_fill[d.y], 1);
    g_csr_src[p1] = s.y;
}

// ---------------- K4b: aggregate x[src] per node via CSR (no atomics) ------
__global__ void k_aggx(const float* __restrict__ x) {
    int n = blockIdx.x * blockDim.x + threadIdx.x;
    if (n >= N_NODES) return;
    int start = __ldg(&g_rowptr[n]);
    int end   = __ldg(&g_rowptr[n + 1]);
    float s0 = 0.f, s1 = 0.f, s2 = 0.f;
    #pragma unroll 4
    for (int i = start; i < end; i++) {
        int s = __ldg(&g_csr_src[i]);
        s0 += __ldg(&x[s * 3 + 0]);
        s1 += __ldg(&x[s * 3 + 1]);
        s2 += __ldg(&x[s * 3 + 2]);
    }
    // slots 4..7 are 16B-aligned; pad (slot 7) is don't-care
    *reinterpret_cast<float4*>(&g_agg8[(size_t)n * 8 + 4]) = make_float4(s0, s1, s2, 0.f);
}

// ---------------- K5: node pass 1 (6->64 linear + ReLU) -> fp16 ------------
// agg8: ea0=a[0] ea1=a[1] ea2=a[2] deg=a[3] x0=a[4] x1=a[5] x2=a[6]
// W1 rows: 0..2 = x features, 3..5 = edge_attr
__global__ void k_node1(const float* __restrict__ W1, const float* __restrict__ b1) {
    __shared__ float sa[16 * 8];
    int tid = threadIdx.x;
    int base = blockIdx.x * 16;
    if (tid < 32)
        reinterpret_cast<float4*>(sa)[tid] =
            reinterpret_cast<const float4*>(&g_agg8[(size_t)base * 8])[tid];
    __syncthreads();
    int nl = tid >> 4;
    int quad = tid & 15;
    const float* a = &sa[nl * 8];
    float oc[4];
    #pragma unroll
    for (int c = 0; c < 4; c++) {
        int j = quad * 4 + c;
        float acc = a[3] * __ldg(&b1[j]);          // deg * b1
        acc += a[4] * __ldg(&W1[0 * 64 + j]);      // x0
        acc += a[5] * __ldg(&W1[1 * 64 + j]);      // x1
        acc += a[6] * __ldg(&W1[2 * 64 + j]);      // x2
        acc += a[0] * __ldg(&W1[3 * 64 + j]);      // ea0
        acc += a[1] * __ldg(&W1[4 * 64 + j]);      // ea1
        acc += a[2] * __ldg(&W1[5 * 64 + j]);      // ea2
        oc[c] = fmaxf(acc, 0.0f);
    }
    __half2 h0 = __floats2half2_rn(oc[0], oc[1]);
    __half2 h1 = __floats2half2_rn(oc[2], oc[3]);
    uint2 packed;
    packed.x = *reinterpret_cast<unsigned*>(&h0);
    packed.y = *reinterpret_cast<unsigned*>(&h1);
    *reinterpret_cast<uint2*>(&g_hh[(size_t)(base + nl) * 64 + quad * 4]) = packed;
}

// ---------------- K6: layer-2 CSR gather, 4 edges/iter, high MLP -----------
__global__ void k_agg2() {
    int warp = (blockIdx.x * blockDim.x + threadIdx.x) >> 5;
    if (warp >= N_NODES) return;
    int lane = threadIdx.x & 31;
    int grp = lane >> 3;
    int oct = lane & 7;
    int start = __ldg(&g_rowptr[warp]);
    int deg   = __ldg(&g_rowptr[warp + 1]) - start;
    float acc[8];
    #pragma unroll
    for (int c = 0; c < 8; c++) acc[c] = 0.0f;

    #pragma unroll 4
    for (int i = grp; i < deg; i += 4) {
        int s = __ldg(&g_csr_src[start + i]);
        uint4 raw = *reinterpret_cast<const uint4*>(&g_hh[(size_t)s * 64 + oct * 8]);
        float2 f0 = __half22float2(*reinterpret_cast<__half2*>(&raw.x));
        float2 f1 = __half22float2(*reinterpret_cast<__half2*>(&raw.y));
        float2 f2 = __half22float2(*reinterpret_cast<__half2*>(&raw.z));
        float2 f3 = __half22float2(*reinterpret_cast<__half2*>(&raw.w));
        acc[0] += f0.x; acc[1] += f0.y; acc[2] += f1.x; acc[3] += f1.y;
        acc[4] += f2.x; acc[5] += f2.y; acc[6] += f3.x; acc[7] += f3.y;
    }
    #pragma unroll
    for (int c = 0; c < 8; c++) {
        acc[c] += __shfl_xor_sync(0xffffffffu, acc[c], 8);
        acc[c] += __shfl_xor_sync(0xffffffffu, acc[c], 16);
    }
    if (grp == 0) {
        float* dst = &g_aggh[(size_t)warp * 64 + oct * 8];
        *reinterpret_cast<float4*>(dst)     = make_float4(acc[0], acc[1], acc[2], acc[3]);
        *reinterpret_cast<float4*>(dst + 4) = make_float4(acc[4], acc[5], acc[6], acc[7]);
    }
}

// ---------------- K7: node pass 2 — FFMA2 register-tiled smem GEMM + head --
#define ASTRIDE 68
#define N2_NODES 64
__global__ void k_node2(const float* __restrict__ W2, const float* __restrict__ b2,
                        const float* __restrict__ W3, const float* __restrict__ b3,
                        float* __restrict__ out) {
    __shared__ float sW[68 * 64];             // rows 0..66: W2, row 67: b2
    __shared__ float sA[N2_NODES * ASTRIDE];  // per node: aggh[64], ea0..2, deg
    int tid = threadIdx.x;
    int nb = blockIdx.x * N2_NODES;

    for (int v = tid; v < 1072; v += 256)
        reinterpret_cast<float4*>(sW)[v] = __ldg(&reinterpret_cast<const float4*>(W2)[v]);
    if (tid < 16)
        reinterpret_cast<float4*>(sW)[1072 + tid] = __ldg(&reinterpret_cast<const float4*>(b2)[tid]);
    for (int v = tid; v < N2_NODES * 16; v += 256) {
        int n = v >> 4, k = v & 15;
        float4 val = make_float4(0.f, 0.f, 0.f, 0.f);
        if (nb + n < N_NODES)
            val = reinterpret_cast<const float4*>(g_aggh)[(size_t)(nb + n) * 16 + k];
        *reinterpret_cast<float4*>(&sA[n * ASTRIDE + k * 4]) = val;
    }
    for (int v = tid; v < N2_NODES; v += 256) {
        float e0 = 0.f, e1 = 0.f, e2 = 0.f, dg = 0.f;
        if (nb + v < N_NODES) {
            const float* a8 = &g_agg8[(size_t)(nb + v) * 8];
            e0 = a8[0]; e1 = a8[1]; e2 = a8[2]; dg = a8[3];
        }
        sA[v * ASTRIDE + 64] = e0;
        sA[v * ASTRIDE + 65] = e1;
        sA[v * ASTRIDE + 66] = e2;
        sA[v * ASTRIDE + 67] = dg;
    }
    __syncthreads();

    int q = tid & 15;
    int g = tid >> 4;
    const float* a0 = &sA[(g * 4 + 0) * ASTRIDE];
    const float* a1 = &sA[(g * 4 + 1) * ASTRIDE];
    const float* a2 = &sA[(g * 4 + 2) * ASTRIDE];
    const float* a3 = &sA[(g * 4 + 3) * ASTRIDE];

    unsigned long long acc00 = 0, acc01 = 0, acc10 = 0, acc11 = 0;
    unsigned long long acc20 = 0, acc21 = 0, acc30 = 0, acc31 = 0;

    #pragma unroll
    for (int i = 0; i < 68; i += 4) {
        float va0[4], va1[4], va2[4], va3[4];
        *reinterpret_cast<float4*>(va0) = *reinterpret_cast<const float4*>(a0 + i);
        *reinterpret_cast<float4*>(va1) = *reinterpret_cast<const float4*>(a1 + i);
        *reinterpret_cast<float4*>(va2) = *reinterpret_cast<const float4*>(a2 + i);
        *reinterpret_cast<float4*>(va3) = *reinterpret_cast<const float4*>(a3 + i);
        #pragma unroll
        for (int k = 0; k < 4; k++) {
            ulonglong2 w = *reinterpret_cast<const ulonglong2*>(&sW[(i + k) * 64 + q * 4]);
            unsigned long long v0p, v1p, v2p, v3p;
            PACK2(v0p, va0[k]);
            PACK2(v1p, va1[k]);
            PACK2(v2p, va2[k]);
            PACK2(v3p, va3[k]);
            FMA2(acc00, v0p, w.x, acc00); FMA2(acc01, v0p, w.y, acc01);
            FMA2(acc10, v1p, w.x, acc10); FMA2(acc11, v1p, w.y, acc11);
            FMA2(acc20, v2p, w.x, acc20); FMA2(acc21, v2p, w.y, acc21);
            FMA2(acc30, v3p, w.x, acc30); FMA2(acc31, v3p, w.y, acc31);
        }
    }

    float w3x = __ldg(&W3[q * 4 + 0]);
    float w3y = __ldg(&W3[q * 4 + 1]);
    float w3z = __ldg(&W3[q * 4 + 2]);
    float w3w = __ldg(&W3[q * 4 + 3]);
    float b3v = __ldg(&b3[0]);

    unsigned long long pl[4][2] = {{acc00, acc01}, {acc10, acc11},
                                   {acc20, acc21}, {acc30, acc31}};
    #pragma unroll
    for (int n = 0; n < 4; n++) {
        float vx, vy, vz, vw;
        UNPACK2(vx, vy, pl[n][0]);
        UNPACK2(vz, vw, pl[n][1]);
        float val = fmaxf(vx, 0.f) * w3x + fmaxf(vy, 0.f) * w3y
                  + fmaxf(vz, 0.f) * w3z + fmaxf(vw, 0.f) * w3w;
        val += __shfl_xor_sync(0xffffffffu, val, 1);
        val += __shfl_xor_sync(0xffffffffu, val, 2);
        val += __shfl_xor_sync(0xffffffffu, val, 4);
        val += __shfl_xor_sync(0xffffffffu, val, 8);
        int node = nb + g * 4 + n;
        if (q == 0 && node < N_NODES)
            out[node] = val + b3v;
    }
}

// ---------------- launch ---------------------------------------------------
extern "C" void kernel_launch(void* const* d_in, const int* in_sizes, int n_in,
                              void* d_out, int out_size) {
    const float* x   = (const float*)d_in[0];
    const void*  ei  = d_in[1];
    const float* ea  = (const float*)d_in[2];
    const float* W1  = (const float*)d_in[3];
    const float* b1  = (const float*)d_in[4];
    const float* W2  = (const float*)d_in[5];
    const float* b2  = (const float*)d_in[6];
    const float* W3  = (const float*)d_in[7];
    const float* b3  = (const float*)d_in[8];
    float* out = (float*)d_out;

    k_detect<<<1, 32>>>((const int*)ei);
    k_zero<<<800, 256>>>();
    k_edge1<<<(N_EDGES / 2 + 255) / 256, 256>>>(ei, ea);
    k_scan_blk<<<NBLK, SCAN_B>>>();
    k_scan_top<<<1, 128>>>();
    k_scan_add<<<(N_NODES + 255) / 256, 256>>>();
    k_scatter<<<(N_EDGES / 2 + 255) / 256, 256>>>();
    k_aggx<<<(N_NODES + 255) / 256, 256>>>(x);
    k_node1<<<N_NODES / 16, 256>>>(W1, b1);
    k_agg2<<<(N_NODES * 32 + 255) / 256, 256>>>();
    k_node2<<<(N_NODES + N2_NODES - 1) / N2_NODES, 256>>>(W2, b2, W3, b3, out);
}

// round 17
// speedup vs baseline: 1.0331x; 1.0331x over previous
#include <cuda_runtime.h>
#include <cuda_fp16.h>
#include <cstdint>

#define N_NODES 100000
#define N_EDGES 1600000
#define HIDDEN  64
#define SCAN_B  1024
#define NBLK    ((N_NODES + SCAN_B - 1) / SCAN_B)   // 98

// ---------------- scratch (static device globals; no runtime alloc) -------
// agg8 layout: [ea0, ea1, ea2, deg, x0, x1, x2, pad]  (x slots unused globally)
__device__ __align__(256) float  g_agg8[N_NODES * 8];
__device__ __align__(256) __half g_hh[N_NODES * HIDDEN];   // layer-1 output (fp16)
__device__ __align__(256) int    g_src[N_EDGES];
__device__ __align__(256) int    g_dst[N_EDGES];
__device__ __align__(256) int    g_csr_src[N_EDGES];       // src ids grouped by dst
__device__ __align__(256) int    g_rowptr[N_NODES];        // start slot per node
__device__ __align__(256) int    g_fill[N_NODES];          // cursor; = end after scatter
__device__ int g_counter;
__device__ int g_is64;

__device__ __forceinline__ void red_add_v4(float* addr, float a, float b, float c, float d) {
    asm volatile(
        "{ .reg .u64 p; cvta.to.global.u64 p, %0;\n"
        "  red.global.add.v4.f32 [p], {%1, %2, %3, %4}; }\n"
        :: "l"(addr), "f"(a), "f"(b), "f"(c), "f"(d) : "memory");
}

// packed f32x2 helpers (FFMA2 path)
#define PACK2(out, v) \
    asm("mov.b64 %0, {%1, %1};" : "=l"(out) : "f"(v))
#define FMA2(d, a, b, c) \
    asm("fma.rn.f32x2 %0, %1, %2, %3;" : "=l"(d) : "l"(a), "l"(b), "l"(c))
#define UNPACK2(lo, hi, in) \
    asm("mov.b64 {%0, %1}, %2;" : "=f"(lo), "=f"(hi) : "l"(in))

// ---------------- K1: zero agg8 + counter + dtype detect -------------------
__global__ void k_zero(const int* __restrict__ ei32) {
    int i = blockIdx.x * blockDim.x + threadIdx.x;
    int stride = gridDim.x * blockDim.x;
    float4 z = make_float4(0.f, 0.f, 0.f, 0.f);
    for (int t = i; t < (N_NODES * 8) / 4; t += stride)
        reinterpret_cast<float4*>(g_agg8)[t] = z;
    if (blockIdx.x == 0 && threadIdx.x < 32) {
        int lane = threadIdx.x;
        int nz = 0;
        if (ei32[4 * lane + 1] != 0) nz = 1;
        if (ei32[4 * lane + 3] != 0) nz = 1;
        unsigned m = __ballot_sync(0xffffffffu, nz);
        if (lane == 0) { g_is64 = (m == 0) ? 1 : 0; g_counter = 0; }
    }
}

// ---------------- K2: edge pass 1 — ONE red.v4 per edge (ea + deg) ---------
__global__ void k_edge1(const void* __restrict__ ei,
                        const float* __restrict__ ea) {
    int t = blockIdx.x * blockDim.x + threadIdx.x;
    int e = 2 * t;
    if (e >= N_EDGES) return;
    int s0, s1, d0, d1;
    if (g_is64) {
        const longlong2* ps = (const longlong2*)ei;
        longlong2 sp = ps[t];
        longlong2 dp = ps[(N_EDGES / 2) + t];
        s0 = (int)sp.x; s1 = (int)sp.y;
        d0 = (int)dp.x; d1 = (int)dp.y;
    } else {
        const int2* ps = (const int2*)ei;
        int2 sp = ps[t];
        int2 dp = ps[(N_EDGES / 2) + t];
        s0 = sp.x; s1 = sp.y;
        d0 = dp.x; d1 = dp.y;
    }
    reinterpret_cast<int2*>(g_src)[t] = make_int2(s0, s1);
    reinterpret_cast<int2*>(g_dst)[t] = make_int2(d0, d1);

    const float2* pea = (const float2*)(ea + 6 * (size_t)t);
    float2 a01 = pea[0];   // e0: ea0 ea1
    float2 a23 = pea[1];   // e0: ea2 | e1: ea0
    float2 a45 = pea[2];   // e1: ea1 ea2

    red_add_v4(&g_agg8[(size_t)d0 * 8], a01.x, a01.y, a23.x, 1.0f);
    red_add_v4(&g_agg8[(size_t)d1 * 8], a23.y, a45.x, a45.y, 1.0f);
}

// ---------------- K3: one-kernel scan (block scan + atomic base) -----------
// rowptr need not be monotonic in node id — any valid partition of [0,E).
__global__ void k_scan() {
    __shared__ int sh[SCAN_B];
    __shared__ int base_sh;
    int t = threadIdx.x;
    int i = blockIdx.x * SCAN_B + t;
    int d = (i < N_NODES) ? (int)g_agg8[(size_t)i * 8 + 3] : 0;
    sh[t] = d;
    __syncthreads();
    #pragma unroll
    for (int off = 1; off < SCAN_B; off <<= 1) {
        int v = (t >= off) ? sh[t - off] : 0;
        __syncthreads();
        sh[t] += v;
        __syncthreads();
    }
    if (t == SCAN_B - 1) base_sh = atomicAdd(&g_counter, sh[t]);
    __syncthreads();
    if (i < N_NODES) {
        int r = base_sh + sh[t] - d;   // exclusive within block + global base
        g_rowptr[i] = r;
        g_fill[i]   = r;
    }
}

// ---------------- K4: scatter src ids into dst-grouped CSR (2 edges/thr) ---
__global__ void k_scatter() {
    int t = blockIdx.x * blockDim.x + threadIdx.x;
    if (2 * t >= N_EDGES) return;
    int2 s = reinterpret_cast<const int2*>(g_src)[t];
    int2 d = reinterpret_cast<const int2*>(g_dst)[t];
    int p0 = atomicAdd(&g_fill[d.x], 1);
    g_csr_src[p0] = s.x;
    int p1 = atomicAdd(&g_fill[d.y], 1);
    g_csr_src[p1] = s.y;
}

// ---------------- K5: node pass 1 — fused x CSR-gather + 6->64 linear ------
// block = 256 threads = 16 nodes. Phase A: 16 threads/node gather x[src].
// Phase B: 16 threads/node compute the 64-wide linear -> fp16 h.
__global__ void k_node1(const float* __restrict__ x,
                        const float* __restrict__ W1, const float* __restrict__ b1) {
    __shared__ float sa[16 * 8];
    int tid = threadIdx.x;
    int base = blockIdx.x * 16;
    if (tid < 32)
        reinterpret_cast<float4*>(sa)[tid] =
            reinterpret_cast<const float4*>(&g_agg8[(size_t)base * 8])[tid];
    __syncthreads();

    int nl = tid >> 4;
    int k  = tid & 15;
    int node = base + nl;

    // phase A: gather-sum x over this node's CSR slots
    {
        int start = __ldg(&g_rowptr[node]);
        int deg   = (int)sa[nl * 8 + 3];
        float s0 = 0.f, s1 = 0.f, s2 = 0.f;
        for (int i = k; i < deg; i += 16) {
            int s = __ldg(&g_csr_src[start + i]);
            s0 += __ldg(&x[s * 3 + 0]);
            s1 += __ldg(&x[s * 3 + 1]);
            s2 += __ldg(&x[s * 3 + 2]);
        }
        #pragma unroll
        for (int off = 1; off < 16; off <<= 1) {
            s0 += __shfl_xor_sync(0xffffffffu, s0, off);
            s1 += __shfl_xor_sync(0xffffffffu, s1, off);
            s2 += __shfl_xor_sync(0xffffffffu, s2, off);
        }
        if (k == 0) {
            sa[nl * 8 + 4] = s0;
            sa[nl * 8 + 5] = s1;
            sa[nl * 8 + 6] = s2;
        }
    }
    __syncthreads();

    // phase B: linear + ReLU -> fp16
    const float* a = &sa[nl * 8];
    float oc[4];
    #pragma unroll
    for (int c = 0; c < 4; c++) {
        int j = k * 4 + c;
        float acc = a[3] * __ldg(&b1[j]);          // deg * b1
        acc += a[4] * __ldg(&W1[0 * 64 + j]);      // x0
        acc += a[5] * __ldg(&W1[1 * 64 + j]);      // x1
        acc += a[6] * __ldg(&W1[2 * 64 + j]);      // x2
        acc += a[0] * __ldg(&W1[3 * 64 + j]);      // ea0
        acc += a[1] * __ldg(&W1[4 * 64 + j]);      // ea1
        acc += a[2] * __ldg(&W1[5 * 64 + j]);      // ea2
        oc[c] = fmaxf(acc, 0.0f);
    }
    __half2 h0 = __floats2half2_rn(oc[0], oc[1]);
    __half2 h1 = __floats2half2_rn(oc[2], oc[3]);
    uint2 packed;
    packed.x = *reinterpret_cast<unsigned*>(&h0);
    packed.y = *reinterpret_cast<unsigned*>(&h1);
    *reinterpret_cast<uint2*>(&g_hh[(size_t)node * 64 + k * 4]) = packed;
}

// ---------------- K6: fused layer-2 aggregation + GEMM + head --------------
// block = 256 threads, 64 nodes. Phase A: 8 warps aggregate h[src] into sA
// (8 nodes per warp, 4 edges in flight, fp16->fp32). Phase B: FFMA2 GEMM.
#define ASTRIDE 68
#define N2_NODES 64
__global__ void k_fuse2(const float* __restrict__ W2, const float* __restrict__ b2,
                        const float* __restrict__ W3, const float* __restrict__ b3,
                        float* __restrict__ out) {
    __shared__ float sW[68 * 64];             // rows 0..66: W2, row 67: b2
    __shared__ float sA[N2_NODES * ASTRIDE];  // per node: aggh[64], ea0..2, deg
    int tid = threadIdx.x;
    int nb = blockIdx.x * N2_NODES;

    // stage W2 + b2
    for (int v = tid; v < 1072; v += 256)
        reinterpret_cast<float4*>(sW)[v] = __ldg(&reinterpret_cast<const float4*>(W2)[v]);
    if (tid < 16)
        reinterpret_cast<float4*>(sW)[1072 + tid] = __ldg(&reinterpret_cast<const float4*>(b2)[tid]);
    // stage ea_agg + deg (slots 64..67 of each sA row)
    for (int v = tid; v < N2_NODES; v += 256) {
        float e0 = 0.f, e1 = 0.f, e2 = 0.f, dg = 0.f;
        if (nb + v < N_NODES) {
            const float* a8 = &g_agg8[(size_t)(nb + v) * 8];
            e0 = a8[0]; e1 = a8[1]; e2 = a8[2]; dg = a8[3];
        }
        sA[v * ASTRIDE + 64] = e0;
        sA[v * ASTRIDE + 65] = e1;
        sA[v * ASTRIDE + 66] = e2;
        sA[v * ASTRIDE + 67] = dg;
    }

    // phase A: neighbor aggregation straight into sA
    {
        int warp = tid >> 5;
        int lane = tid & 31;
        int grp = lane >> 3;
        int oct = lane & 7;
        #pragma unroll
        for (int j = 0; j < 8; j++) {
            int nl = warp * 8 + j;
            int node = nb + nl;
            float acc[8];
            #pragma unroll
            for (int c = 0; c < 8; c++) acc[c] = 0.0f;
            if (node < N_NODES) {
                int start = __ldg(&g_rowptr[node]);
                int deg   = __ldg(&g_fill[node]) - start;   // fill = end after scatter
                #pragma unroll 4
                for (int i = grp; i < deg; i += 4) {
                    int s = __ldg(&g_csr_src[start + i]);
                    uint4 raw = *reinterpret_cast<const uint4*>(&g_hh[(size_t)s * 64 + oct * 8]);
                    float2 f0 = __half22float2(*reinterpret_cast<__half2*>(&raw.x));
                    float2 f1 = __half22float2(*reinterpret_cast<__half2*>(&raw.y));
                    float2 f2 = __half22float2(*reinterpret_cast<__half2*>(&raw.z));
                    float2 f3 = __half22float2(*reinterpret_cast<__half2*>(&raw.w));
                    acc[0] += f0.x; acc[1] += f0.y; acc[2] += f1.x; acc[3] += f1.y;
                    acc[4] += f2.x; acc[5] += f2.y; acc[6] += f3.x; acc[7] += f3.y;
                }
            }
            #pragma unroll
            for (int c = 0; c < 8; c++) {
                acc[c] += __shfl_xor_sync(0xffffffffu, acc[c], 8);
                acc[c] += __shfl_xor_sync(0xffffffffu, acc[c], 16);
            }
            if (grp == 0) {
                float* dst = &sA[nl * ASTRIDE + oct * 8];
                *reinterpret_cast<float4*>(dst)     = make_float4(acc[0], acc[1], acc[2], acc[3]);
                *reinterpret_cast<float4*>(dst + 4) = make_float4(acc[4], acc[5], acc[6], acc[7]);
            }
        }
    }
    __syncthreads();

    // phase B: FFMA2 register-tiled GEMM + head
    int q = tid & 15;
    int g = tid >> 4;
    const float* a0 = &sA[(g * 4 + 0) * ASTRIDE];
    const float* a1 = &sA[(g * 4 + 1) * ASTRIDE];
    const float* a2 = &sA[(g * 4 + 2) * ASTRIDE];
    const float* a3 = &sA[(g * 4 + 3) * ASTRIDE];

    unsigned long long acc00 = 0, acc01 = 0, acc10 = 0, acc11 = 0;
    unsigned long long acc20 = 0, acc21 = 0, acc30 = 0, acc31 = 0;

    #pragma unroll
    for (int i = 0; i < 68; i += 4) {
        float va0[4], va1[4], va2[4], va3[4];
        *reinterpret_cast<float4*>(va0) = *reinterpret_cast<const float4*>(a0 + i);
        *reinterpret_cast<float4*>(va1) = *reinterpret_cast<const float4*>(a1 + i);
        *reinterpret_cast<float4*>(va2) = *reinterpret_cast<const float4*>(a2 + i);
        *reinterpret_cast<float4*>(va3) = *reinterpret_cast<const float4*>(a3 + i);
        #pragma unroll
        for (int k = 0; k < 4; k++) {
            ulonglong2 w = *reinterpret_cast<const ulonglong2*>(&sW[(i + k) * 64 + q * 4]);
            unsigned long long v0p, v1p, v2p, v3p;
            PACK2(v0p, va0[k]);
            PACK2(v1p, va1[k]);
            PACK2(v2p, va2[k]);
            PACK2(v3p, va3[k]);
            FMA2(acc00, v0p, w.x, acc00); FMA2(acc01, v0p, w.y, acc01);
            FMA2(acc10, v1p, w.x, acc10); FMA2(acc11, v1p, w.y, acc11);
            FMA2(acc20, v2p, w.x, acc20); FMA2(acc21, v2p, w.y, acc21);
            FMA2(acc30, v3p, w.x, acc30); FMA2(acc31, v3p, w.y, acc31);
        }
    }

    float w3x = __ldg(&W3[q * 4 + 0]);
    float w3y = __ldg(&W3[q * 4 + 1]);
    float w3z = __ldg(&W3[q * 4 + 2]);
    float w3w = __ldg(&W3[q * 4 + 3]);
    float b3v = __ldg(&b3[0]);

    unsigned long long pl[4][2] = {{acc00, acc01}, {acc10, acc11},
                                   {acc20, acc21}, {acc30, acc31}};
    #pragma unroll
    for (int n = 0; n < 4; n++) {
        float vx, vy, vz, vw;
        UNPACK2(vx, vy, pl[n][0]);
        UNPACK2(vz, vw, pl[n][1]);
        float val = fmaxf(vx, 0.f) * w3x + fmaxf(vy, 0.f) * w3y
                  + fmaxf(vz, 0.f) * w3z + fmaxf(vw, 0.f) * w3w;
        val += __shfl_xor_sync(0xffffffffu, val, 1);
        val += __shfl_xor_sync(0xffffffffu, val, 2);
        val += __shfl_xor_sync(0xffffffffu, val, 4);
        val += __shfl_xor_sync(0xffffffffu, val, 8);
        int node = nb + g * 4 + n;
        if (q == 0 && node < N_NODES)
            out[node] = val + b3v;
    }
}

// ---------------- launch ---------------------------------------------------
extern "C" void kernel_launch(void* const* d_in, const int* in_sizes, int n_in,
                              void* d_out, int out_size) {
    const float* x   = (const float*)d_in[0];
    const void*  ei  = d_in[1];
    const float* ea  = (const float*)d_in[2];
    const float* W1  = (const float*)d_in[3];
    const float* b1  = (const float*)d_in[4];
    const float* W2  = (const float*)d_in[5];
    const float* b2  = (const float*)d_in[6];
    const float* W3  = (const float*)d_in[7];
    const float* b3  = (const float*)d_in[8];
    float* out = (float*)d_out;

    k_zero<<<800, 256>>>((const int*)ei);
    k_edge1<<<(N_EDGES / 2 + 255) / 256, 256>>>(ei, ea);
    k_scan<<<NBLK, SCAN_B>>>();
    k_scatter<<<(N_EDGES / 2 + 255) / 256, 256>>>();
    k_node1<<<N_NODES / 16, 256>>>(x, W1, b1);
    k_fuse2<<<(N_NODES + N2_NODES - 1) / N2_NODES, 256>>>(W2, b2, W3, b3, out);
}